// round 2
// baseline (speedup 1.0000x reference)
#include <cuda_runtime.h>
#include <cuda_bf16.h>
#include <cstdint>
#include <cstddef>

#define T_TOK 200704          // 4096 * 49 tokens
#define DIMC  192
#define NHD   6
#define HDIM  32
#define NTOK  49
#define NQKV  576
#define SCALEA 0.17677669529663687f

// ---------------- device scratch (static; no runtime allocation) -------------
__device__ float g_qkv[(size_t)T_TOK * NQKV];
__device__ float g_ao [(size_t)T_TOK * DIMC];
__device__ __nv_bfloat16 g_wqkvT_h[NQKV * DIMC];
__device__ __nv_bfloat16 g_wqkvT_l[NQKV * DIMC];
__device__ __nv_bfloat16 g_wprojT_h[DIMC * DIMC];
__device__ __nv_bfloat16 g_wprojT_l[DIMC * DIMC];
__device__ float g_bias6[NHD * NTOK * NTOK];

// ---------------- helpers ----------------------------------------------------
__device__ __forceinline__ uint32_t packbf(__nv_bfloat16 a, __nv_bfloat16 b) {
    __nv_bfloat162 t(a, b);
    return *reinterpret_cast<uint32_t*>(&t);
}

__device__ __forceinline__ void mma16816(float* c, const uint32_t* a,
                                         uint32_t b0, uint32_t b1) {
    asm volatile(
        "mma.sync.aligned.m16n8k16.row.col.f32.bf16.bf16.f32 "
        "{%0,%1,%2,%3},{%4,%5,%6,%7},{%8,%9},{%0,%1,%2,%3};"
        : "+f"(c[0]), "+f"(c[1]), "+f"(c[2]), "+f"(c[3])
        : "r"(a[0]), "r"(a[1]), "r"(a[2]), "r"(a[3]), "r"(b0), "r"(b1));
}

// ---------------- prep: split weights + pre-gather bias ----------------------
__global__ void prep_kernel(const float* __restrict__ qkv_w,
                            const float* __restrict__ proj_w,
                            const float* __restrict__ bias_table,
                            const int*   __restrict__ rel_idx) {
    const int n1 = NQKV * DIMC, n2 = DIMC * DIMC, n3 = NHD * NTOK * NTOK;
    for (int i = blockIdx.x * blockDim.x + threadIdx.x; i < n1 + n2 + n3;
         i += gridDim.x * blockDim.x) {
        if (i < n1) {
            int n = i / DIMC, k = i % DIMC;
            float w = qkv_w[k * NQKV + n];
            __nv_bfloat16 h = __float2bfloat16(w);
            g_wqkvT_h[i] = h;
            g_wqkvT_l[i] = __float2bfloat16(w - __bfloat162float(h));
        } else if (i < n1 + n2) {
            int j = i - n1;
            int n = j / DIMC, k = j % DIMC;
            float w = proj_w[k * DIMC + n];
            __nv_bfloat16 h = __float2bfloat16(w);
            g_wprojT_h[j] = h;
            g_wprojT_l[j] = __float2bfloat16(w - __bfloat162float(h));
        } else {
            int j = i - n1 - n2;
            int h6 = j / (NTOK * NTOK);
            int rc = j % (NTOK * NTOK);
            g_bias6[j] = bias_table[rel_idx[rc] * NHD + h6];
        }
    }
}

// ---------------- GEMM: C[M,Nc] = A[M,192] * W^T + bias ----------------------
#define BM 128
#define BN 96
#define SSTR 200
#define GEMM_SMEM ((2 * BM + 2 * BN) * SSTR * 2)

__global__ __launch_bounds__(256, 1)
void gemm_kernel(const float* __restrict__ Ain,   // null -> g_ao
                 const float* __restrict__ bias,
                 float* __restrict__ Cout,        // null -> g_qkv
                 int Nc, int useProjW) {
    extern __shared__ __nv_bfloat16 smb[];
    __nv_bfloat16* Ah = smb;
    __nv_bfloat16* Al = Ah + BM * SSTR;
    __nv_bfloat16* Bh = Al + BM * SSTR;
    __nv_bfloat16* Bl = Bh + BN * SSTR;

    const float* A = Ain ? Ain : g_ao;
    float* C = Cout ? Cout : g_qkv;
    const __nv_bfloat16* Bhg = useProjW ? g_wprojT_h : g_wqkvT_h;
    const __nv_bfloat16* Blg = useProjW ? g_wprojT_l : g_wqkvT_l;

    const int tid = threadIdx.x;
    const int rbase = blockIdx.x * BM;
    const int nbase = blockIdx.y * BN;

    for (int i = tid; i < BM * 48; i += 256) {       // A: 128 rows x 48 float4
        int row = i / 48, j = i % 48;
        float4 v = *(const float4*)(A + (size_t)(rbase + row) * DIMC + j * 4);
        __nv_bfloat16 h0 = __float2bfloat16(v.x), h1 = __float2bfloat16(v.y);
        __nv_bfloat16 h2 = __float2bfloat16(v.z), h3 = __float2bfloat16(v.w);
        __nv_bfloat16 l0 = __float2bfloat16(v.x - __bfloat162float(h0));
        __nv_bfloat16 l1 = __float2bfloat16(v.y - __bfloat162float(h1));
        __nv_bfloat16 l2 = __float2bfloat16(v.z - __bfloat162float(h2));
        __nv_bfloat16 l3 = __float2bfloat16(v.w - __bfloat162float(h3));
        *(uint2*)(Ah + row * SSTR + j * 4) = make_uint2(packbf(h0, h1), packbf(h2, h3));
        *(uint2*)(Al + row * SSTR + j * 4) = make_uint2(packbf(l0, l1), packbf(l2, l3));
    }
    for (int i = tid; i < BN * 24; i += 256) {       // B: 96 rows x 24 uint4
        int row = i / 24, j = i % 24;
        *(uint4*)(Bh + row * SSTR + j * 8) =
            *(const uint4*)(Bhg + (size_t)(nbase + row) * DIMC + j * 8);
        *(uint4*)(Bl + row * SSTR + j * 8) =
            *(const uint4*)(Blg + (size_t)(nbase + row) * DIMC + j * 8);
    }
    __syncthreads();

    const int lane = tid & 31, warp = tid >> 5;
    const int g = lane >> 2, tg = lane & 3;
    const int mb = (warp >> 1) * 32;
    const int nb = (warp & 1) * 48;

    float acc[2][6][4];
#pragma unroll
    for (int mt = 0; mt < 2; mt++)
#pragma unroll
        for (int nt = 0; nt < 6; nt++)
#pragma unroll
            for (int r = 0; r < 4; r++) acc[mt][nt][r] = 0.f;

#pragma unroll
    for (int part = 0; part < 3; part++) {
        const __nv_bfloat16* As = (part == 1) ? Al : Ah;
        const __nv_bfloat16* Bs = (part == 2) ? Bl : Bh;
#pragma unroll
        for (int kk = 0; kk < 12; kk++) {
            uint32_t a[2][4];
#pragma unroll
            for (int mt = 0; mt < 2; mt++) {
                const __nv_bfloat16* p = As + (mb + mt * 16 + g) * SSTR + kk * 16 + tg * 2;
                a[mt][0] = *(const uint32_t*)(p);
                a[mt][1] = *(const uint32_t*)(p + 8 * SSTR);
                a[mt][2] = *(const uint32_t*)(p + 8);
                a[mt][3] = *(const uint32_t*)(p + 8 * SSTR + 8);
            }
#pragma unroll
            for (int nt = 0; nt < 6; nt++) {
                const __nv_bfloat16* p = Bs + (nb + nt * 8 + g) * SSTR + kk * 16 + tg * 2;
                uint32_t b0 = *(const uint32_t*)(p);
                uint32_t b1 = *(const uint32_t*)(p + 8);
#pragma unroll
                for (int mt = 0; mt < 2; mt++)
                    mma16816(acc[mt][nt], a[mt], b0, b1);
            }
        }
    }

#pragma unroll
    for (int mt = 0; mt < 2; mt++) {
        int row0 = rbase + mb + mt * 16 + g;
#pragma unroll
        for (int nt = 0; nt < 6; nt++) {
            int col = nbase + nb + nt * 8 + tg * 2;
            float b0 = bias[col], b1 = bias[col + 1];
            *(float2*)(C + (size_t)row0 * Nc + col) =
                make_float2(acc[mt][nt][0] + b0, acc[mt][nt][1] + b1);
            *(float2*)(C + (size_t)(row0 + 8) * Nc + col) =
                make_float2(acc[mt][nt][2] + b0, acc[mt][nt][3] + b1);
        }
    }
}

// ---------------- attention: one CTA per (window, head) ----------------------
__global__ __launch_bounds__(128)
void attn_kernel() {
    __shared__ __nv_bfloat16 sm2[14848];
    __nv_bfloat16* Qh  = sm2;               // [64][40]
    __nv_bfloat16* Ql  = sm2 + 2560;
    __nv_bfloat16* Kh  = sm2 + 5120;        // [64][40]
    __nv_bfloat16* Kl  = sm2 + 7680;
    __nv_bfloat16* Vth = sm2 + 10240;       // [32][72]  V^T: [d][tok]
    __nv_bfloat16* Vtl = sm2 + 12544;

    const int b = blockIdx.x, h = blockIdx.y;
    const int tid = threadIdx.x;

    for (int i = tid; i < 7424; i += 128) ((uint32_t*)sm2)[i] = 0u;
    __syncthreads();

    const float* src = g_qkv + (size_t)b * NTOK * NQKV + h * HDIM;
    for (int i = tid; i < 3 * NTOK * 8; i += 128) {
        int which = i / (NTOK * 8);
        int j = i % (NTOK * 8);
        int row = j / 8, seg = j % 8;
        float4 v = *(const float4*)(src + row * NQKV + which * DIMC + seg * 4);
        __nv_bfloat16 h0 = __float2bfloat16(v.x), h1 = __float2bfloat16(v.y);
        __nv_bfloat16 h2 = __float2bfloat16(v.z), h3 = __float2bfloat16(v.w);
        __nv_bfloat16 l0 = __float2bfloat16(v.x - __bfloat162float(h0));
        __nv_bfloat16 l1 = __float2bfloat16(v.y - __bfloat162float(h1));
        __nv_bfloat16 l2 = __float2bfloat16(v.z - __bfloat162float(h2));
        __nv_bfloat16 l3 = __float2bfloat16(v.w - __bfloat162float(h3));
        if (which < 2) {
            __nv_bfloat16* dh = (which == 0) ? Qh : Kh;
            __nv_bfloat16* dl = (which == 0) ? Ql : Kl;
            *(uint2*)(dh + row * 40 + seg * 4) = make_uint2(packbf(h0, h1), packbf(h2, h3));
            *(uint2*)(dl + row * 40 + seg * 4) = make_uint2(packbf(l0, l1), packbf(l2, l3));
        } else {
            int d = seg * 4;
            Vth[(d + 0) * 72 + row] = h0; Vtl[(d + 0) * 72 + row] = l0;
            Vth[(d + 1) * 72 + row] = h1; Vtl[(d + 1) * 72 + row] = l1;
            Vth[(d + 2) * 72 + row] = h2; Vtl[(d + 2) * 72 + row] = l2;
            Vth[(d + 3) * 72 + row] = h3; Vtl[(d + 3) * 72 + row] = l3;
        }
    }
    __syncthreads();

    const int lane = tid & 31, w = tid >> 5;
    const int g = lane >> 2, tg = lane & 3;

    // ---- S = Q K^T (3-term split). Warp owns rows w*16..w*16+15, 8 n-tiles --
    float s[8][4];
#pragma unroll
    for (int nt = 0; nt < 8; nt++)
#pragma unroll
        for (int r = 0; r < 4; r++) s[nt][r] = 0.f;

#pragma unroll
    for (int part = 0; part < 3; part++) {
        const __nv_bfloat16* Qs = (part == 1) ? Ql : Qh;
        const __nv_bfloat16* Ks = (part == 2) ? Kl : Kh;
#pragma unroll
        for (int kk = 0; kk < 2; kk++) {
            uint32_t a[4];
            const __nv_bfloat16* p = Qs + (w * 16 + g) * 40 + kk * 16 + tg * 2;
            a[0] = *(const uint32_t*)(p);
            a[1] = *(const uint32_t*)(p + 8 * 40);
            a[2] = *(const uint32_t*)(p + 8);
            a[3] = *(const uint32_t*)(p + 8 * 40 + 8);
#pragma unroll
            for (int nt = 0; nt < 8; nt++) {
                const __nv_bfloat16* q = Ks + (nt * 8 + g) * 40 + kk * 16 + tg * 2;
                mma16816(s[nt], a, *(const uint32_t*)(q), *(const uint32_t*)(q + 8));
            }
        }
    }

    // ---- scale + bias + mask ----
    const float* bias_h = g_bias6 + h * (NTOK * NTOK);
    const int r0 = w * 16 + g, r1 = r0 + 8;
#pragma unroll
    for (int nt = 0; nt < 8; nt++) {
#pragma unroll
        for (int j = 0; j < 2; j++) {
            int col = nt * 8 + tg * 2 + j;
            if (col < NTOK) {
                s[nt][j]     = s[nt][j]     * SCALEA + (r0 < NTOK ? bias_h[r0 * NTOK + col] : 0.f);
                s[nt][2 + j] = s[nt][2 + j] * SCALEA + (r1 < NTOK ? bias_h[r1 * NTOK + col] : 0.f);
            } else {
                s[nt][j] = -1e30f;
                s[nt][2 + j] = -1e30f;
            }
        }
    }

    // ---- softmax (row r0 lives in c0/c1, row r1 in c2/c3; reduce over quad) --
    float m0 = -1e30f, m1 = -1e30f;
#pragma unroll
    for (int nt = 0; nt < 8; nt++) {
        m0 = fmaxf(m0, fmaxf(s[nt][0], s[nt][1]));
        m1 = fmaxf(m1, fmaxf(s[nt][2], s[nt][3]));
    }
    m0 = fmaxf(m0, __shfl_xor_sync(0xffffffffu, m0, 1));
    m0 = fmaxf(m0, __shfl_xor_sync(0xffffffffu, m0, 2));
    m1 = fmaxf(m1, __shfl_xor_sync(0xffffffffu, m1, 1));
    m1 = fmaxf(m1, __shfl_xor_sync(0xffffffffu, m1, 2));
    float d0 = 0.f, d1 = 0.f;
#pragma unroll
    for (int nt = 0; nt < 8; nt++) {
        s[nt][0] = __expf(s[nt][0] - m0); d0 += s[nt][0];
        s[nt][1] = __expf(s[nt][1] - m0); d0 += s[nt][1];
        s[nt][2] = __expf(s[nt][2] - m1); d1 += s[nt][2];
        s[nt][3] = __expf(s[nt][3] - m1); d1 += s[nt][3];
    }
    d0 += __shfl_xor_sync(0xffffffffu, d0, 1);
    d0 += __shfl_xor_sync(0xffffffffu, d0, 2);
    d1 += __shfl_xor_sync(0xffffffffu, d1, 1);
    d1 += __shfl_xor_sync(0xffffffffu, d1, 2);
    const float inv0 = 1.f / d0, inv1 = 1.f / d1;

    // ---- P fragments (hi/lo split); S-accum layout == A-fragment layout -----
    uint32_t aPh[4][4], aPl[4][4];
#pragma unroll
    for (int kc = 0; kc < 4; kc++) {
#pragma unroll
        for (int t2 = 0; t2 < 2; t2++) {
            int tile = 2 * kc + t2;
            float p0 = s[tile][0] * inv0, p1 = s[tile][1] * inv0;
            float p2 = s[tile][2] * inv1, p3 = s[tile][3] * inv1;
            __nv_bfloat16 h0 = __float2bfloat16(p0), h1 = __float2bfloat16(p1);
            __nv_bfloat16 h2 = __float2bfloat16(p2), h3 = __float2bfloat16(p3);
            aPh[kc][t2]     = packbf(h0, h1);
            aPh[kc][t2 + 2] = packbf(h2, h3);   // note reg order fixed below
            aPl[kc][t2]     = packbf(__float2bfloat16(p0 - __bfloat162float(h0)),
                                     __float2bfloat16(p1 - __bfloat162float(h1)));
            aPl[kc][t2 + 2] = packbf(__float2bfloat16(p2 - __bfloat162float(h2)),
                                     __float2bfloat16(p3 - __bfloat162float(h3)));
        }
    }
    // A-fragment reg order is {r0k0, r8k0, r0k8, r8k8}: swap regs 1<->2
#pragma unroll
    for (int kc = 0; kc < 4; kc++) {
        uint32_t t = aPh[kc][1]; aPh[kc][1] = aPh[kc][2]; aPh[kc][2] = t;
        t = aPl[kc][1]; aPl[kc][1] = aPl[kc][2]; aPl[kc][2] = t;
    }

    // ---- O = P V (3-term split) ----
    float o[4][4];
#pragma unroll
    for (int nt = 0; nt < 4; nt++)
#pragma unroll
        for (int r = 0; r < 4; r++) o[nt][r] = 0.f;

#pragma unroll
    for (int part = 0; part < 3; part++) {
        const uint32_t (*Ap)[4] = (part == 1) ? aPl : aPh;
        const __nv_bfloat16* Vs = (part == 2) ? Vtl : Vth;
#pragma unroll
        for (int kc = 0; kc < 4; kc++) {
#pragma unroll
            for (int nt = 0; nt < 4; nt++) {
                const __nv_bfloat16* p = Vs + (nt * 8 + g) * 72 + kc * 16 + tg * 2;
                mma16816(o[nt], Ap[kc], *(const uint32_t*)(p), *(const uint32_t*)(p + 8));
            }
        }
    }

    // ---- store to g_ao ----
#pragma unroll
    for (int nt = 0; nt < 4; nt++) {
        int d = h * HDIM + nt * 8 + tg * 2;
        if (r0 < NTOK)
            *(float2*)(g_ao + ((size_t)b * NTOK + r0) * DIMC + d) = make_float2(o[nt][0], o[nt][1]);
        if (r1 < NTOK)
            *(float2*)(g_ao + ((size_t)b * NTOK + r1) * DIMC + d) = make_float2(o[nt][2], o[nt][3]);
    }
}

// ---------------- launch ------------------------------------------------------
extern "C" void kernel_launch(void* const* d_in, const int* in_sizes, int n_in,
                              void* d_out, int out_size) {
    const float* x          = (const float*)d_in[0];
    const float* qkv_w      = (const float*)d_in[1];
    const float* qkv_b      = (const float*)d_in[2];
    const float* proj_w     = (const float*)d_in[3];
    const float* proj_b     = (const float*)d_in[4];
    const float* bias_table = (const float*)d_in[5];
    const int*   rel_idx    = (const int*)d_in[6];
    float* out = (float*)d_out;

    static bool attr_set = false;
    if (!attr_set) {
        cudaFuncSetAttribute(gemm_kernel, cudaFuncAttributeMaxDynamicSharedMemorySize,
                             GEMM_SMEM);
        attr_set = true;
    }

    prep_kernel<<<640, 256>>>(qkv_w, proj_w, bias_table, rel_idx);

    dim3 g1(T_TOK / BM, NQKV / BN);
    gemm_kernel<<<g1, 256, GEMM_SMEM>>>(x, qkv_b, nullptr, NQKV, 0);

    dim3 g2(4096, NHD);
    attn_kernel<<<g2, 128>>>();

    dim3 g3(T_TOK / BM, DIMC / BN);
    gemm_kernel<<<g3, 256, GEMM_SMEM>>>(nullptr, proj_b, out, DIMC, 1);
}

// round 4
// speedup vs baseline: 1.3983x; 1.3983x over previous
#include <cuda_runtime.h>
#include <cuda_bf16.h>
#include <cstdint>
#include <cstddef>

#define T_TOK 200704          // 4096 * 49 tokens
#define DIMC  192
#define NHD   6
#define HDIM  32
#define NTOK  49
#define NQKV  576
#define SCALEA 0.17677669529663687f

// ---------------- device scratch (static; no runtime allocation) -------------
__device__ float g_qkv[(size_t)T_TOK * NQKV];                 // fp32 qkv
__device__ __nv_bfloat16 g_xh[(size_t)T_TOK * DIMC];          // x split hi
__device__ __nv_bfloat16 g_xl[(size_t)T_TOK * DIMC];          // x split lo
__device__ __nv_bfloat16 g_aoh[(size_t)T_TOK * DIMC];         // attn out hi
__device__ __nv_bfloat16 g_aol[(size_t)T_TOK * DIMC];         // attn out lo
__device__ __nv_bfloat16 g_wqkvT_h[NQKV * DIMC];
__device__ __nv_bfloat16 g_wqkvT_l[NQKV * DIMC];
__device__ __nv_bfloat16 g_wprojT_h[DIMC * DIMC];
__device__ __nv_bfloat16 g_wprojT_l[DIMC * DIMC];
__device__ float g_bias6[NHD * NTOK * NTOK];

// ---------------- helpers ----------------------------------------------------
__device__ __forceinline__ uint32_t packbf(__nv_bfloat16 a, __nv_bfloat16 b) {
    __nv_bfloat162 t(a, b);
    return *reinterpret_cast<uint32_t*>(&t);
}

__device__ __forceinline__ void mma16816(float* c, const uint32_t* a,
                                         uint32_t b0, uint32_t b1) {
    asm volatile(
        "mma.sync.aligned.m16n8k16.row.col.f32.bf16.bf16.f32 "
        "{%0,%1,%2,%3},{%4,%5,%6,%7},{%8,%9},{%0,%1,%2,%3};"
        : "+f"(c[0]), "+f"(c[1]), "+f"(c[2]), "+f"(c[3])
        : "r"(a[0]), "r"(a[1]), "r"(a[2]), "r"(a[3]), "r"(b0), "r"(b1));
}

__device__ __forceinline__ void ldsm4(uint32_t* r, uint32_t addr) {
    asm volatile("ldmatrix.sync.aligned.m8n8.x4.shared.b16 {%0,%1,%2,%3}, [%4];"
                 : "=r"(r[0]), "=r"(r[1]), "=r"(r[2]), "=r"(r[3]) : "r"(addr));
}

__device__ __forceinline__ void ldsm2(uint32_t& r0, uint32_t& r1, uint32_t addr) {
    asm volatile("ldmatrix.sync.aligned.m8n8.x2.shared.b16 {%0,%1}, [%2];"
                 : "=r"(r0), "=r"(r1) : "r"(addr));
}

__device__ __forceinline__ void cpa16(uint32_t smem, const void* gptr) {
    asm volatile("cp.async.cg.shared.global [%0], [%1], 16;\n"
                 :: "r"(smem), "l"(gptr));
}
__device__ __forceinline__ void cp_commit() {
    asm volatile("cp.async.commit_group;\n" ::: "memory");
}
__device__ __forceinline__ void cp_wait0() {
    asm volatile("cp.async.wait_group 0;\n" ::: "memory");
}

__device__ __forceinline__ uint32_t s2u(const void* p) {
    return (uint32_t)__cvta_generic_to_shared(p);
}

// ---------------- prep: split weights + pre-gather bias ----------------------
__global__ void prep_kernel(const float* __restrict__ qkv_w,
                            const float* __restrict__ proj_w,
                            const float* __restrict__ bias_table,
                            const int*   __restrict__ rel_idx) {
    const int n1 = NQKV * DIMC, n2 = DIMC * DIMC, n3 = NHD * NTOK * NTOK;
    for (int i = blockIdx.x * blockDim.x + threadIdx.x; i < n1 + n2 + n3;
         i += gridDim.x * blockDim.x) {
        if (i < n1) {
            int n = i / DIMC, k = i % DIMC;
            float w = qkv_w[k * NQKV + n];
            __nv_bfloat16 h = __float2bfloat16(w);
            g_wqkvT_h[i] = h;
            g_wqkvT_l[i] = __float2bfloat16(w - __bfloat162float(h));
        } else if (i < n1 + n2) {
            int j = i - n1;
            int n = j / DIMC, k = j % DIMC;
            float w = proj_w[k * DIMC + n];
            __nv_bfloat16 h = __float2bfloat16(w);
            g_wprojT_h[j] = h;
            g_wprojT_l[j] = __float2bfloat16(w - __bfloat162float(h));
        } else {
            int j = i - n1 - n2;
            int h6 = j / (NTOK * NTOK);
            int rc = j % (NTOK * NTOK);
            g_bias6[j] = bias_table[rel_idx[rc] * NHD + h6];
        }
    }
}

// ---------------- xsplit: x fp32 -> bf16 hi/lo --------------------------------
__global__ void xsplit_kernel(const float* __restrict__ x) {
    const size_t n4 = (size_t)T_TOK * DIMC / 4;
    for (size_t i = blockIdx.x * blockDim.x + threadIdx.x; i < n4;
         i += (size_t)gridDim.x * blockDim.x) {
        float4 v = ((const float4*)x)[i];
        __nv_bfloat16 h0 = __float2bfloat16(v.x), h1 = __float2bfloat16(v.y);
        __nv_bfloat16 h2 = __float2bfloat16(v.z), h3 = __float2bfloat16(v.w);
        __nv_bfloat16 l0 = __float2bfloat16(v.x - __bfloat162float(h0));
        __nv_bfloat16 l1 = __float2bfloat16(v.y - __bfloat162float(h1));
        __nv_bfloat16 l2 = __float2bfloat16(v.z - __bfloat162float(h2));
        __nv_bfloat16 l3 = __float2bfloat16(v.w - __bfloat162float(h3));
        ((uint2*)g_xh)[i] = make_uint2(packbf(h0, h1), packbf(h2, h3));
        ((uint2*)g_xl)[i] = make_uint2(packbf(l0, l1), packbf(l2, l3));
    }
}

// ---------------- GEMM: C[64-row tile, Nc] = A[64,192] * W^T + bias ----------
// A (bf16 hi/lo) staged once in smem; loop over 48-col B chunks (cp.async).
#define GBM   64
#define GSTR  200                       // smem row stride in halves
#define SM_A  (GBM * GSTR)              // 12800 halves per A buffer
#define SM_B  (48 * GSTR)               // 9600 halves per B buffer
#define GEMM_SMEM ((2 * SM_A + 2 * SM_B) * 2)   // 89600 bytes

__global__ __launch_bounds__(256, 2)
void gemm_kernel(float* __restrict__ Cout, const float* __restrict__ bias,
                 int Nc, int nChunks, int mode) {
    extern __shared__ __nv_bfloat16 smb[];
    __nv_bfloat16* Ah = smb;
    __nv_bfloat16* Al = smb + SM_A;
    __nv_bfloat16* Bh = smb + 2 * SM_A;
    __nv_bfloat16* Bl = smb + 2 * SM_A + SM_B;

    const __nv_bfloat16* Agh = mode ? g_aoh : g_xh;
    const __nv_bfloat16* Agl = mode ? g_aol : g_xl;
    const __nv_bfloat16* Bgh = mode ? g_wprojT_h : g_wqkvT_h;
    const __nv_bfloat16* Bgl = mode ? g_wprojT_l : g_wqkvT_l;
    float* C = mode ? Cout : g_qkv;

    const int tid = threadIdx.x;
    const size_t rbase = (size_t)blockIdx.x * GBM;

    // A: 64 rows x 24 16B segments, hi + lo
    for (int i = tid; i < GBM * 24; i += 256) {
        int row = i / 24, j = i % 24;
        const size_t go = (rbase + row) * DIMC + j * 8;
        cpa16(s2u(Ah + row * GSTR + j * 8), Agh + go);
        cpa16(s2u(Al + row * GSTR + j * 8), Agl + go);
    }
    // B chunk 0: 48 rows x 24 segments, hi + lo
    for (int i = tid; i < 48 * 24; i += 256) {
        int row = i / 24, j = i % 24;
        const size_t go = (size_t)row * DIMC + j * 8;
        cpa16(s2u(Bh + row * GSTR + j * 8), Bgh + go);
        cpa16(s2u(Bl + row * GSTR + j * 8), Bgl + go);
    }
    cp_commit();
    cp_wait0();
    __syncthreads();

    const int lane = tid & 31, warp = tid >> 5;
    const int g = lane >> 2, tg = lane & 3;
    const int m0 = (warp >> 1) * 16;        // 4 warps over M=64
    const int n0 = (warp & 1) * 24;         // 2 warps over 48-col chunk

    // ldmatrix lane addresses
    const int aRow = m0 + (lane & 15);
    const int aK   = (lane >> 4) * 8;
    const int b4Row = n0 + (lane & 7) + ((lane >> 4) << 3);
    const int bK    = ((lane >> 3) & 1) * 8;
    const int b2Row = n0 + 16 + (lane & 7);

    const uint32_t aBaseH  = s2u(Ah + aRow * GSTR + aK);
    const uint32_t aBaseL  = aBaseH + SM_A * 2;
    const uint32_t b4BaseH = s2u(Bh + b4Row * GSTR + bK);
    const uint32_t b4BaseL = b4BaseH + SM_B * 2;
    const uint32_t b2BaseH = s2u(Bh + b2Row * GSTR + bK);
    const uint32_t b2BaseL = b2BaseH + SM_B * 2;

    for (int c = 0; c < nChunks; c++) {
        float acc[3][4];
#pragma unroll
        for (int nt = 0; nt < 3; nt++)
#pragma unroll
            for (int r = 0; r < 4; r++) acc[nt][r] = 0.f;

#pragma unroll
        for (int part = 0; part < 3; part++) {
            const uint32_t aB = (part == 1) ? aBaseL : aBaseH;
            const uint32_t b4 = (part == 2) ? b4BaseL : b4BaseH;
            const uint32_t b2 = (part == 2) ? b2BaseL : b2BaseH;
#pragma unroll
            for (int kk = 0; kk < 12; kk++) {
                uint32_t a[4], b[6];
                ldsm4(a, aB + kk * 32);
                ldsm4(b, b4 + kk * 32);
                ldsm2(b[4], b[5], b2 + kk * 32);
                mma16816(acc[0], a, b[0], b[1]);
                mma16816(acc[1], a, b[2], b[3]);
                mma16816(acc[2], a, b[4], b[5]);
            }
        }
        __syncthreads();                    // done reading B chunk c

        if (c + 1 < nChunks) {              // prefetch next B chunk
            for (int i = tid; i < 48 * 24; i += 256) {
                int row = i / 24, j = i % 24;
                const size_t go = (size_t)((c + 1) * 48 + row) * DIMC + j * 8;
                cpa16(s2u(Bh + row * GSTR + j * 8), Bgh + go);
                cpa16(s2u(Bl + row * GSTR + j * 8), Bgl + go);
            }
            cp_commit();
        }

        // epilogue for chunk c (overlaps in-flight cp.async)
        const int colBase = c * 48 + n0;
        const size_t r0 = rbase + m0 + g;
#pragma unroll
        for (int nt = 0; nt < 3; nt++) {
            int col = colBase + nt * 8 + tg * 2;
            float b0 = bias[col], b1 = bias[col + 1];
            *(float2*)(C + r0 * Nc + col) =
                make_float2(acc[nt][0] + b0, acc[nt][1] + b1);
            *(float2*)(C + (r0 + 8) * Nc + col) =
                make_float2(acc[nt][2] + b0, acc[nt][3] + b1);
        }

        if (c + 1 < nChunks) {
            cp_wait0();
            __syncthreads();
        }
    }
}

// ---------------- attention: one CTA per (window, head) ----------------------
__global__ __launch_bounds__(128)
void attn_kernel() {
    __shared__ __nv_bfloat16 sm2[14848];
    __nv_bfloat16* Qh  = sm2;               // [64][40]
    __nv_bfloat16* Ql  = sm2 + 2560;
    __nv_bfloat16* Kh  = sm2 + 5120;        // [64][40]
    __nv_bfloat16* Kl  = sm2 + 7680;
    __nv_bfloat16* Vth = sm2 + 10240;       // [32][72]  V^T: [d][tok]
    __nv_bfloat16* Vtl = sm2 + 12544;

    const int b = blockIdx.x, h = blockIdx.y;
    const int tid = threadIdx.x;

    for (int i = tid; i < 7424; i += 128) ((uint32_t*)sm2)[i] = 0u;
    __syncthreads();

    const float* src = g_qkv + (size_t)b * NTOK * NQKV + h * HDIM;
    for (int i = tid; i < 3 * NTOK * 8; i += 128) {
        int which = i / (NTOK * 8);
        int j = i % (NTOK * 8);
        int row = j / 8, seg = j % 8;
        float4 v = *(const float4*)(src + row * NQKV + which * DIMC + seg * 4);
        __nv_bfloat16 h0 = __float2bfloat16(v.x), h1 = __float2bfloat16(v.y);
        __nv_bfloat16 h2 = __float2bfloat16(v.z), h3 = __float2bfloat16(v.w);
        __nv_bfloat16 l0 = __float2bfloat16(v.x - __bfloat162float(h0));
        __nv_bfloat16 l1 = __float2bfloat16(v.y - __bfloat162float(h1));
        __nv_bfloat16 l2 = __float2bfloat16(v.z - __bfloat162float(h2));
        __nv_bfloat16 l3 = __float2bfloat16(v.w - __bfloat162float(h3));
        if (which < 2) {
            __nv_bfloat16* dh = (which == 0) ? Qh : Kh;
            __nv_bfloat16* dl = (which == 0) ? Ql : Kl;
            *(uint2*)(dh + row * 40 + seg * 4) = make_uint2(packbf(h0, h1), packbf(h2, h3));
            *(uint2*)(dl + row * 40 + seg * 4) = make_uint2(packbf(l0, l1), packbf(l2, l3));
        } else {
            int d = seg * 4;
            Vth[(d + 0) * 72 + row] = h0; Vtl[(d + 0) * 72 + row] = l0;
            Vth[(d + 1) * 72 + row] = h1; Vtl[(d + 1) * 72 + row] = l1;
            Vth[(d + 2) * 72 + row] = h2; Vtl[(d + 2) * 72 + row] = l2;
            Vth[(d + 3) * 72 + row] = h3; Vtl[(d + 3) * 72 + row] = l3;
        }
    }
    __syncthreads();

    const int lane = tid & 31, w = tid >> 5;
    const int g = lane >> 2, tg = lane & 3;

    // ---- S = Q K^T (3-term split). Warp owns rows w*16..w*16+15, 8 n-tiles --
    float s[8][4];
#pragma unroll
    for (int nt = 0; nt < 8; nt++)
#pragma unroll
        for (int r = 0; r < 4; r++) s[nt][r] = 0.f;

#pragma unroll
    for (int part = 0; part < 3; part++) {
        const __nv_bfloat16* Qs = (part == 1) ? Ql : Qh;
        const __nv_bfloat16* Ks = (part == 2) ? Kl : Kh;
#pragma unroll
        for (int kk = 0; kk < 2; kk++) {
            uint32_t a[4];
            const __nv_bfloat16* p = Qs + (w * 16 + g) * 40 + kk * 16 + tg * 2;
            a[0] = *(const uint32_t*)(p);
            a[1] = *(const uint32_t*)(p + 8 * 40);
            a[2] = *(const uint32_t*)(p + 8);
            a[3] = *(const uint32_t*)(p + 8 * 40 + 8);
#pragma unroll
            for (int nt = 0; nt < 8; nt++) {
                const __nv_bfloat16* q = Ks + (nt * 8 + g) * 40 + kk * 16 + tg * 2;
                mma16816(s[nt], a, *(const uint32_t*)(q), *(const uint32_t*)(q + 8));
            }
        }
    }

    // ---- scale + bias + mask ----
    const float* bias_h = g_bias6 + h * (NTOK * NTOK);
    const int r0 = w * 16 + g, r1 = r0 + 8;
#pragma unroll
    for (int nt = 0; nt < 8; nt++) {
#pragma unroll
        for (int j = 0; j < 2; j++) {
            int col = nt * 8 + tg * 2 + j;
            if (col < NTOK) {
                s[nt][j]     = s[nt][j]     * SCALEA + (r0 < NTOK ? bias_h[r0 * NTOK + col] : 0.f);
                s[nt][2 + j] = s[nt][2 + j] * SCALEA + (r1 < NTOK ? bias_h[r1 * NTOK + col] : 0.f);
            } else {
                s[nt][j] = -1e30f;
                s[nt][2 + j] = -1e30f;
            }
        }
    }

    // ---- softmax ----
    float m0 = -1e30f, m1 = -1e30f;
#pragma unroll
    for (int nt = 0; nt < 8; nt++) {
        m0 = fmaxf(m0, fmaxf(s[nt][0], s[nt][1]));
        m1 = fmaxf(m1, fmaxf(s[nt][2], s[nt][3]));
    }
    m0 = fmaxf(m0, __shfl_xor_sync(0xffffffffu, m0, 1));
    m0 = fmaxf(m0, __shfl_xor_sync(0xffffffffu, m0, 2));
    m1 = fmaxf(m1, __shfl_xor_sync(0xffffffffu, m1, 1));
    m1 = fmaxf(m1, __shfl_xor_sync(0xffffffffu, m1, 2));
    float d0 = 0.f, d1 = 0.f;
#pragma unroll
    for (int nt = 0; nt < 8; nt++) {
        s[nt][0] = __expf(s[nt][0] - m0); d0 += s[nt][0];
        s[nt][1] = __expf(s[nt][1] - m0); d0 += s[nt][1];
        s[nt][2] = __expf(s[nt][2] - m1); d1 += s[nt][2];
        s[nt][3] = __expf(s[nt][3] - m1); d1 += s[nt][3];
    }
    d0 += __shfl_xor_sync(0xffffffffu, d0, 1);
    d0 += __shfl_xor_sync(0xffffffffu, d0, 2);
    d1 += __shfl_xor_sync(0xffffffffu, d1, 1);
    d1 += __shfl_xor_sync(0xffffffffu, d1, 2);
    const float inv0 = 1.f / d0, inv1 = 1.f / d1;

    // ---- P fragments (hi/lo split) ----
    uint32_t aPh[4][4], aPl[4][4];
#pragma unroll
    for (int kc = 0; kc < 4; kc++) {
#pragma unroll
        for (int t2 = 0; t2 < 2; t2++) {
            int tile = 2 * kc + t2;
            float p0 = s[tile][0] * inv0, p1 = s[tile][1] * inv0;
            float p2 = s[tile][2] * inv1, p3 = s[tile][3] * inv1;
            __nv_bfloat16 h0 = __float2bfloat16(p0), h1 = __float2bfloat16(p1);
            __nv_bfloat16 h2 = __float2bfloat16(p2), h3 = __float2bfloat16(p3);
            aPh[kc][t2]     = packbf(h0, h1);
            aPh[kc][t2 + 2] = packbf(h2, h3);
            aPl[kc][t2]     = packbf(__float2bfloat16(p0 - __bfloat162float(h0)),
                                     __float2bfloat16(p1 - __bfloat162float(h1)));
            aPl[kc][t2 + 2] = packbf(__float2bfloat16(p2 - __bfloat162float(h2)),
                                     __float2bfloat16(p3 - __bfloat162float(h3)));
        }
    }
#pragma unroll
    for (int kc = 0; kc < 4; kc++) {
        uint32_t t = aPh[kc][1]; aPh[kc][1] = aPh[kc][2]; aPh[kc][2] = t;
        t = aPl[kc][1]; aPl[kc][1] = aPl[kc][2]; aPl[kc][2] = t;
    }

    // ---- O = P V (3-term split) ----
    float o[4][4];
#pragma unroll
    for (int nt = 0; nt < 4; nt++)
#pragma unroll
        for (int r = 0; r < 4; r++) o[nt][r] = 0.f;

#pragma unroll
    for (int part = 0; part < 3; part++) {
        const uint32_t (*Ap)[4] = (part == 1) ? aPl : aPh;
        const __nv_bfloat16* Vs = (part == 2) ? Vtl : Vth;
#pragma unroll
        for (int kc = 0; kc < 4; kc++) {
#pragma unroll
            for (int nt = 0; nt < 4; nt++) {
                const __nv_bfloat16* p = Vs + (nt * 8 + g) * 72 + kc * 16 + tg * 2;
                mma16816(o[nt], Ap[kc], *(const uint32_t*)(p), *(const uint32_t*)(p + 8));
            }
        }
    }

    // ---- store bf16 hi/lo (same split gemm2 would have computed from fp32) --
#pragma unroll
    for (int nt = 0; nt < 4; nt++) {
        int d = h * HDIM + nt * 8 + tg * 2;
        if (r0 < NTOK) {
            size_t off = ((size_t)b * NTOK + r0) * DIMC + d;
            __nv_bfloat16 h0 = __float2bfloat16(o[nt][0]);
            __nv_bfloat16 h1 = __float2bfloat16(o[nt][1]);
            *(uint32_t*)(g_aoh + off) = packbf(h0, h1);
            *(uint32_t*)(g_aol + off) =
                packbf(__float2bfloat16(o[nt][0] - __bfloat162float(h0)),
                       __float2bfloat16(o[nt][1] - __bfloat162float(h1)));
        }
        if (r1 < NTOK) {
            size_t off = ((size_t)b * NTOK + r1) * DIMC + d;
            __nv_bfloat16 h2 = __float2bfloat16(o[nt][2]);
            __nv_bfloat16 h3 = __float2bfloat16(o[nt][3]);
            *(uint32_t*)(g_aoh + off) = packbf(h2, h3);
            *(uint32_t*)(g_aol + off) =
                packbf(__float2bfloat16(o[nt][2] - __bfloat162float(h2)),
                       __float2bfloat16(o[nt][3] - __bfloat162float(h3)));
        }
    }
}

// ---------------- launch ------------------------------------------------------
extern "C" void kernel_launch(void* const* d_in, const int* in_sizes, int n_in,
                              void* d_out, int out_size) {
    const float* x          = (const float*)d_in[0];
    const float* qkv_w      = (const float*)d_in[1];
    const float* qkv_b      = (const float*)d_in[2];
    const float* proj_w     = (const float*)d_in[3];
    const float* proj_b     = (const float*)d_in[4];
    const float* bias_table = (const float*)d_in[5];
    const int*   rel_idx    = (const int*)d_in[6];
    float* out = (float*)d_out;

    static bool attr_set = false;
    if (!attr_set) {
        cudaFuncSetAttribute(gemm_kernel, cudaFuncAttributeMaxDynamicSharedMemorySize,
                             GEMM_SMEM);
        attr_set = true;
    }

    prep_kernel<<<640, 256>>>(qkv_w, proj_w, bias_table, rel_idx);
    xsplit_kernel<<<2368, 256>>>(x);

    gemm_kernel<<<T_TOK / GBM, 256, GEMM_SMEM>>>(nullptr, qkv_b, NQKV, 12, 0);

    dim3 g2(4096, NHD);
    attn_kernel<<<g2, 128>>>();

    gemm_kernel<<<T_TOK / GBM, 256, GEMM_SMEM>>>(out, proj_b, DIMC, 4, 1);
}

// round 5
// speedup vs baseline: 1.4486x; 1.0360x over previous
#include <cuda_runtime.h>
#include <cuda_bf16.h>
#include <cstdint>
#include <cstddef>

#define T_TOK 200704          // 4096 * 49 tokens
#define DIMC  192
#define NHD   6
#define HDIM  32
#define NTOK  49
#define NQKV  576
#define SCALEA 0.17677669529663687f
#define BIAS_STRIDE 2404      // 49*49 padded to 16B multiple (floats)

// ---------------- device scratch (static; no runtime allocation) -------------
__device__ __nv_bfloat16 g_qkvh[(size_t)T_TOK * NQKV];   // [b][which][h][tok][d]
__device__ __nv_bfloat16 g_qkvl[(size_t)T_TOK * NQKV];
__device__ __nv_bfloat16 g_aoh[(size_t)T_TOK * DIMC];    // attn out hi [t][c]
__device__ __nv_bfloat16 g_aol[(size_t)T_TOK * DIMC];
__device__ __nv_bfloat16 g_wqkvT_h[NQKV * DIMC];
__device__ __nv_bfloat16 g_wqkvT_l[NQKV * DIMC];
__device__ __nv_bfloat16 g_wprojT_h[DIMC * DIMC];
__device__ __nv_bfloat16 g_wprojT_l[DIMC * DIMC];
__device__ float g_bias6[NHD * BIAS_STRIDE];

// ---------------- helpers ----------------------------------------------------
__device__ __forceinline__ uint32_t packbf(__nv_bfloat16 a, __nv_bfloat16 b) {
    __nv_bfloat162 t(a, b);
    return *reinterpret_cast<uint32_t*>(&t);
}

__device__ __forceinline__ void mma16816(float* c, const uint32_t* a,
                                         uint32_t b0, uint32_t b1) {
    asm volatile(
        "mma.sync.aligned.m16n8k16.row.col.f32.bf16.bf16.f32 "
        "{%0,%1,%2,%3},{%4,%5,%6,%7},{%8,%9},{%0,%1,%2,%3};"
        : "+f"(c[0]), "+f"(c[1]), "+f"(c[2]), "+f"(c[3])
        : "r"(a[0]), "r"(a[1]), "r"(a[2]), "r"(a[3]), "r"(b0), "r"(b1));
}

__device__ __forceinline__ void ldsm4(uint32_t* r, uint32_t addr) {
    asm volatile("ldmatrix.sync.aligned.m8n8.x4.shared.b16 {%0,%1,%2,%3}, [%4];"
                 : "=r"(r[0]), "=r"(r[1]), "=r"(r[2]), "=r"(r[3]) : "r"(addr));
}

__device__ __forceinline__ void ldsm4t(uint32_t* r, uint32_t addr) {
    asm volatile("ldmatrix.sync.aligned.m8n8.x4.trans.shared.b16 {%0,%1,%2,%3}, [%4];"
                 : "=r"(r[0]), "=r"(r[1]), "=r"(r[2]), "=r"(r[3]) : "r"(addr));
}

__device__ __forceinline__ void ldsm2(uint32_t& r0, uint32_t& r1, uint32_t addr) {
    asm volatile("ldmatrix.sync.aligned.m8n8.x2.shared.b16 {%0,%1}, [%2];"
                 : "=r"(r0), "=r"(r1) : "r"(addr));
}

__device__ __forceinline__ void cpa16(uint32_t smem, const void* gptr) {
    asm volatile("cp.async.cg.shared.global [%0], [%1], 16;\n"
                 :: "r"(smem), "l"(gptr));
}
__device__ __forceinline__ void cp_commit() {
    asm volatile("cp.async.commit_group;\n" ::: "memory");
}
__device__ __forceinline__ void cp_wait0() {
    asm volatile("cp.async.wait_group 0;\n" ::: "memory");
}

__device__ __forceinline__ uint32_t s2u(const void* p) {
    return (uint32_t)__cvta_generic_to_shared(p);
}

// ---------------- prep: split weights + pre-gather bias ----------------------
__global__ void prep_kernel(const float* __restrict__ qkv_w,
                            const float* __restrict__ proj_w,
                            const float* __restrict__ bias_table,
                            const int*   __restrict__ rel_idx) {
    const int n1 = NQKV * DIMC, n2 = DIMC * DIMC, n3 = NHD * NTOK * NTOK;
    for (int i = blockIdx.x * blockDim.x + threadIdx.x; i < n1 + n2 + n3;
         i += gridDim.x * blockDim.x) {
        if (i < n1) {
            int n = i / DIMC, k = i % DIMC;
            float w = qkv_w[k * NQKV + n];
            __nv_bfloat16 h = __float2bfloat16(w);
            g_wqkvT_h[i] = h;
            g_wqkvT_l[i] = __float2bfloat16(w - __bfloat162float(h));
        } else if (i < n1 + n2) {
            int j = i - n1;
            int n = j / DIMC, k = j % DIMC;
            float w = proj_w[k * DIMC + n];
            __nv_bfloat16 h = __float2bfloat16(w);
            g_wprojT_h[j] = h;
            g_wprojT_l[j] = __float2bfloat16(w - __bfloat162float(h));
        } else {
            int j = i - n1 - n2;
            int h6 = j / (NTOK * NTOK);
            int rc = j % (NTOK * NTOK);
            g_bias6[h6 * BIAS_STRIDE + rc] = bias_table[rel_idx[rc] * NHD + h6];
        }
    }
}

// ---------------- GEMM ------------------------------------------------------
// mode 0: A = x fp32 (split in prologue), C = qkv bf16 hi/lo, Nc=576, 12 chunks
// mode 1: A = g_aoh/g_aol bf16,           C = out fp32,       Nc=192, 4 chunks
#define GBM   64
#define GSTR  200                       // smem row stride in halves
#define SM_A  (GBM * GSTR)              // halves per A buffer
#define SM_B  (48 * GSTR)               // halves per B buffer
#define GEMM_SMEM ((2 * SM_A + 2 * SM_B) * 2)   // 89600 bytes

__global__ __launch_bounds__(256, 2)
void gemm_kernel(const float* __restrict__ Ax, float* __restrict__ Cout,
                 const float* __restrict__ bias, int Nc, int nChunks, int mode) {
    extern __shared__ __nv_bfloat16 smb[];
    __nv_bfloat16* Ah = smb;
    __nv_bfloat16* Al = smb + SM_A;
    __nv_bfloat16* Bh = smb + 2 * SM_A;
    __nv_bfloat16* Bl = smb + 2 * SM_A + SM_B;

    const __nv_bfloat16* Bgh = mode ? g_wprojT_h : g_wqkvT_h;
    const __nv_bfloat16* Bgl = mode ? g_wprojT_l : g_wqkvT_l;

    const int tid = threadIdx.x;
    const size_t rbase = (size_t)blockIdx.x * GBM;

    // B chunk 0 first (async), then A
    for (int i = tid; i < 48 * 24; i += 256) {
        int row = i / 24, j = i % 24;
        const size_t go = (size_t)row * DIMC + j * 8;
        cpa16(s2u(Bh + row * GSTR + j * 8), Bgh + go);
        cpa16(s2u(Bl + row * GSTR + j * 8), Bgl + go);
    }
    cp_commit();

    if (mode == 0) {
        // A: fp32 x, convert+split into smem
        for (int i = tid; i < GBM * 48; i += 256) {
            int row = i / 48, j = i % 48;
            float4 v = *(const float4*)(Ax + (rbase + row) * DIMC + j * 4);
            __nv_bfloat16 h0 = __float2bfloat16(v.x), h1 = __float2bfloat16(v.y);
            __nv_bfloat16 h2 = __float2bfloat16(v.z), h3 = __float2bfloat16(v.w);
            __nv_bfloat16 l0 = __float2bfloat16(v.x - __bfloat162float(h0));
            __nv_bfloat16 l1 = __float2bfloat16(v.y - __bfloat162float(h1));
            __nv_bfloat16 l2 = __float2bfloat16(v.z - __bfloat162float(h2));
            __nv_bfloat16 l3 = __float2bfloat16(v.w - __bfloat162float(h3));
            *(uint2*)(Ah + row * GSTR + j * 4) = make_uint2(packbf(h0, h1), packbf(h2, h3));
            *(uint2*)(Al + row * GSTR + j * 4) = make_uint2(packbf(l0, l1), packbf(l2, l3));
        }
    } else {
        for (int i = tid; i < GBM * 24; i += 256) {
            int row = i / 24, j = i % 24;
            const size_t go = (rbase + row) * DIMC + j * 8;
            cpa16(s2u(Ah + row * GSTR + j * 8), g_aoh + go);
            cpa16(s2u(Al + row * GSTR + j * 8), g_aol + go);
        }
        cp_commit();
    }
    cp_wait0();
    __syncthreads();

    const int lane = tid & 31, warp = tid >> 5;
    const int g = lane >> 2, tg = lane & 3;
    const int m0 = (warp >> 1) * 16;        // 4 warps over M=64
    const int n0 = (warp & 1) * 24;         // 2 warps over 48-col chunk

    const int aRow = m0 + (lane & 15);
    const int aK   = (lane >> 4) * 8;
    const int b4Row = n0 + (lane & 7) + ((lane >> 4) << 3);
    const int bK    = ((lane >> 3) & 1) * 8;
    const int b2Row = n0 + 16 + (lane & 7);

    const uint32_t aBaseH  = s2u(Ah + aRow * GSTR + aK);
    const uint32_t aBaseL  = aBaseH + SM_A * 2;
    const uint32_t b4BaseH = s2u(Bh + b4Row * GSTR + bK);
    const uint32_t b4BaseL = b4BaseH + SM_B * 2;
    const uint32_t b2BaseH = s2u(Bh + b2Row * GSTR + bK);
    const uint32_t b2BaseL = b2BaseH + SM_B * 2;

    for (int c = 0; c < nChunks; c++) {
        float acc[3][4];
#pragma unroll
        for (int nt = 0; nt < 3; nt++)
#pragma unroll
            for (int r = 0; r < 4; r++) acc[nt][r] = 0.f;

#pragma unroll
        for (int part = 0; part < 3; part++) {
            const uint32_t aB = (part == 1) ? aBaseL : aBaseH;
            const uint32_t b4 = (part == 2) ? b4BaseL : b4BaseH;
            const uint32_t b2 = (part == 2) ? b2BaseL : b2BaseH;
#pragma unroll
            for (int kk = 0; kk < 12; kk++) {
                uint32_t a[4], b[6];
                ldsm4(a, aB + kk * 32);
                ldsm4(b, b4 + kk * 32);
                ldsm2(b[4], b[5], b2 + kk * 32);
                mma16816(acc[0], a, b[0], b[1]);
                mma16816(acc[1], a, b[2], b[3]);
                mma16816(acc[2], a, b[4], b[5]);
            }
        }
        __syncthreads();                    // done reading B chunk c

        if (c + 1 < nChunks) {              // prefetch next B chunk
            for (int i = tid; i < 48 * 24; i += 256) {
                int row = i / 24, j = i % 24;
                const size_t go = (size_t)((c + 1) * 48 + row) * DIMC + j * 8;
                cpa16(s2u(Bh + row * GSTR + j * 8), Bgh + go);
                cpa16(s2u(Bl + row * GSTR + j * 8), Bgl + go);
            }
            cp_commit();
        }

        // epilogue for chunk c (overlaps in-flight cp.async)
        const int colBase = c * 48 + n0;
        const size_t r0 = rbase + m0 + g;
        if (mode == 0) {
#pragma unroll
            for (int nt = 0; nt < 3; nt++) {
                int col = colBase + nt * 8 + tg * 2;
                int which = col / DIMC;
                int rem = col - which * DIMC;
                int hh = rem >> 5, d = rem & 31;
                float bb0 = bias[col], bb1 = bias[col + 1];
#pragma unroll
                for (int rr = 0; rr < 2; rr++) {
                    size_t r = r0 + rr * 8;
                    int bwin = (int)(r / NTOK);
                    int tok = (int)(r - (size_t)bwin * NTOK);
                    size_t off = ((((size_t)bwin * 3 + which) * NHD + hh) * NTOK + tok)
                                 * HDIM + d;
                    float v0 = acc[nt][rr * 2 + 0] + bb0;
                    float v1 = acc[nt][rr * 2 + 1] + bb1;
                    __nv_bfloat16 h0 = __float2bfloat16(v0);
                    __nv_bfloat16 h1 = __float2bfloat16(v1);
                    *(uint32_t*)(g_qkvh + off) = packbf(h0, h1);
                    *(uint32_t*)(g_qkvl + off) =
                        packbf(__float2bfloat16(v0 - __bfloat162float(h0)),
                               __float2bfloat16(v1 - __bfloat162float(h1)));
                }
            }
        } else {
#pragma unroll
            for (int nt = 0; nt < 3; nt++) {
                int col = colBase + nt * 8 + tg * 2;
                float bb0 = bias[col], bb1 = bias[col + 1];
                *(float2*)(Cout + r0 * Nc + col) =
                    make_float2(acc[nt][0] + bb0, acc[nt][1] + bb1);
                *(float2*)(Cout + (r0 + 8) * Nc + col) =
                    make_float2(acc[nt][2] + bb0, acc[nt][3] + bb1);
            }
        }

        if (c + 1 < nChunks) {
            cp_wait0();
            __syncthreads();
        }
    }
}

// ---------------- attention: one CTA per (window, head) ----------------------
// smem buffers: Qh Ql Kh Kl Vh Vl, each 49 rows x 40 halves (stride 80 B)
#define ABUF 1960                 // halves per buffer
#define AB_B 3920                 // bytes per buffer

__global__ __launch_bounds__(128, 6)
void attn_kernel() {
    __shared__ __nv_bfloat16 sQKV[6 * ABUF];
    __shared__ float sBias[BIAS_STRIDE];

    const int b = blockIdx.x, h = blockIdx.y;
    const int tid = threadIdx.x;
    const uint32_t sBase = s2u(sQKV);
    const uint32_t sBiasU = s2u(sBias);

    // ---- cp.async loads: 6 qkv slabs (each 3136 B contiguous) + bias --------
    {
        const size_t slabStride = (size_t)NTOK * HDIM;               // 1568
        const size_t base = ((size_t)b * 3 * NHD + h) * slabStride;  // which=0
        const float* biasg = g_bias6 + h * BIAS_STRIDE;
        for (int i = tid; i < 6 * 196 + 601; i += 128) {
            if (i < 6 * 196) {
                int s = i / 196, j = i - s * 196;
                int which = s >> 1;
                const __nv_bfloat16* src =
                    ((s & 1) ? g_qkvl : g_qkvh) + base + (size_t)which * NHD * slabStride
                    + j * 8;
                cpa16(sBase + s * AB_B + (j >> 2) * 80 + (j & 3) * 16, src);
            } else {
                int j = i - 6 * 196;
                cpa16(sBiasU + j * 16, biasg + j * 4);
            }
        }
        cp_commit();
    }

    const int lane = tid & 31, w = tid >> 5;
    const int g = lane >> 2, tg = lane & 3;

    // ldmatrix lane offsets (bytes), rows clamped to 48 (real data; masked later)
    const int qRow = w * 16 + (lane & 15);
    const uint32_t qOff = (uint32_t)(min(qRow, 48) * 80 + (lane >> 4) * 16);
    const int kR = (lane & 7) + ((lane >> 4) << 3);
    const int kC = ((lane >> 3) & 1) * 16;
    const int vR0 = (lane & 7) + (((lane >> 3) & 1) << 3);
    const int vC = (lane >> 4) * 16;

    cp_wait0();
    __syncthreads();

    // ---- S = Q K^T (3-term split). 8 n-tiles (cols 0..63) -------------------
    float s[8][4];
#pragma unroll
    for (int nt = 0; nt < 8; nt++)
#pragma unroll
        for (int r = 0; r < 4; r++) s[nt][r] = 0.f;

#pragma unroll
    for (int part = 0; part < 3; part++) {
        const uint32_t qB = sBase + ((part == 1) ? AB_B : 0) + qOff;
        const uint32_t kB = sBase + 2 * AB_B + ((part == 2) ? AB_B : 0);
#pragma unroll
        for (int kk = 0; kk < 2; kk++) {
            uint32_t a[4];
            ldsm4(a, qB + kk * 32);
#pragma unroll
            for (int p = 0; p < 4; p++) {
                uint32_t bfr[4];
                ldsm4(bfr, kB + (uint32_t)(min(p * 16 + kR, 48) * 80 + kC) + kk * 32);
                mma16816(s[2 * p], a, bfr[0], bfr[1]);
                mma16816(s[2 * p + 1], a, bfr[2], bfr[3]);
            }
        }
    }

    // ---- scale + bias + mask ----
    const int r0 = w * 16 + g, r1 = r0 + 8;
#pragma unroll
    for (int nt = 0; nt < 8; nt++) {
#pragma unroll
        for (int j = 0; j < 2; j++) {
            int col = nt * 8 + tg * 2 + j;
            if (col < NTOK) {
                s[nt][j]     = s[nt][j]     * SCALEA + (r0 < NTOK ? sBias[r0 * NTOK + col] : 0.f);
                s[nt][2 + j] = s[nt][2 + j] * SCALEA + (r1 < NTOK ? sBias[r1 * NTOK + col] : 0.f);
            } else {
                s[nt][j] = -1e30f;
                s[nt][2 + j] = -1e30f;
            }
        }
    }

    // ---- softmax ----
    float m0 = -1e30f, m1 = -1e30f;
#pragma unroll
    for (int nt = 0; nt < 8; nt++) {
        m0 = fmaxf(m0, fmaxf(s[nt][0], s[nt][1]));
        m1 = fmaxf(m1, fmaxf(s[nt][2], s[nt][3]));
    }
    m0 = fmaxf(m0, __shfl_xor_sync(0xffffffffu, m0, 1));
    m0 = fmaxf(m0, __shfl_xor_sync(0xffffffffu, m0, 2));
    m1 = fmaxf(m1, __shfl_xor_sync(0xffffffffu, m1, 1));
    m1 = fmaxf(m1, __shfl_xor_sync(0xffffffffu, m1, 2));
    float d0 = 0.f, d1 = 0.f;
#pragma unroll
    for (int nt = 0; nt < 8; nt++) {
        s[nt][0] = __expf(s[nt][0] - m0); d0 += s[nt][0];
        s[nt][1] = __expf(s[nt][1] - m0); d0 += s[nt][1];
        s[nt][2] = __expf(s[nt][2] - m1); d1 += s[nt][2];
        s[nt][3] = __expf(s[nt][3] - m1); d1 += s[nt][3];
    }
    d0 += __shfl_xor_sync(0xffffffffu, d0, 1);
    d0 += __shfl_xor_sync(0xffffffffu, d0, 2);
    d1 += __shfl_xor_sync(0xffffffffu, d1, 1);
    d1 += __shfl_xor_sync(0xffffffffu, d1, 2);
    const float inv0 = 1.f / d0, inv1 = 1.f / d1;

    // ---- P fragments (hi/lo split); S-accum layout == A-fragment layout -----
    uint32_t aPh[4][4], aPl[4][4];
#pragma unroll
    for (int kc = 0; kc < 4; kc++) {
#pragma unroll
        for (int t2 = 0; t2 < 2; t2++) {
            int tile = 2 * kc + t2;
            float p0 = s[tile][0] * inv0, p1 = s[tile][1] * inv0;
            float p2 = s[tile][2] * inv1, p3 = s[tile][3] * inv1;
            __nv_bfloat16 h0 = __float2bfloat16(p0), h1 = __float2bfloat16(p1);
            __nv_bfloat16 h2 = __float2bfloat16(p2), h3 = __float2bfloat16(p3);
            aPh[kc][t2]     = packbf(h0, h1);
            aPh[kc][t2 + 2] = packbf(h2, h3);
            aPl[kc][t2]     = packbf(__float2bfloat16(p0 - __bfloat162float(h0)),
                                     __float2bfloat16(p1 - __bfloat162float(h1)));
            aPl[kc][t2 + 2] = packbf(__float2bfloat16(p2 - __bfloat162float(h2)),
                                     __float2bfloat16(p3 - __bfloat162float(h3)));
        }
    }
    // A-fragment reg order {r0k0, r8k0, r0k8, r8k8}: swap regs 1<->2
#pragma unroll
    for (int kc = 0; kc < 4; kc++) {
        uint32_t t = aPh[kc][1]; aPh[kc][1] = aPh[kc][2]; aPh[kc][2] = t;
        t = aPl[kc][1]; aPl[kc][1] = aPl[kc][2]; aPl[kc][2] = t;
    }

    // ---- O = P V (3-term split), V via ldmatrix.trans -----------------------
    float o[4][4];
#pragma unroll
    for (int nt = 0; nt < 4; nt++)
#pragma unroll
        for (int r = 0; r < 4; r++) o[nt][r] = 0.f;

#pragma unroll
    for (int part = 0; part < 3; part++) {
        const uint32_t (*Ap)[4] = (part == 1) ? aPl : aPh;
        const uint32_t vB = sBase + 4 * AB_B + ((part == 2) ? AB_B : 0);
#pragma unroll
        for (int kc = 0; kc < 4; kc++) {
            const uint32_t rowOff = (uint32_t)(min(vR0 + kc * 16, 48) * 80 + vC);
#pragma unroll
            for (int dh = 0; dh < 2; dh++) {
                uint32_t bv[4];
                ldsm4t(bv, vB + rowOff + dh * 32);
                mma16816(o[dh * 2 + 0], Ap[kc], bv[0], bv[1]);
                mma16816(o[dh * 2 + 1], Ap[kc], bv[2], bv[3]);
            }
        }
    }

    // ---- store bf16 hi/lo ----
#pragma unroll
    for (int nt = 0; nt < 4; nt++) {
        int d = h * HDIM + nt * 8 + tg * 2;
        if (r0 < NTOK) {
            size_t off = ((size_t)b * NTOK + r0) * DIMC + d;
            __nv_bfloat16 h0 = __float2bfloat16(o[nt][0]);
            __nv_bfloat16 h1 = __float2bfloat16(o[nt][1]);
            *(uint32_t*)(g_aoh + off) = packbf(h0, h1);
            *(uint32_t*)(g_aol + off) =
                packbf(__float2bfloat16(o[nt][0] - __bfloat162float(h0)),
                       __float2bfloat16(o[nt][1] - __bfloat162float(h1)));
        }
        if (r1 < NTOK) {
            size_t off = ((size_t)b * NTOK + r1) * DIMC + d;
            __nv_bfloat16 h2 = __float2bfloat16(o[nt][2]);
            __nv_bfloat16 h3 = __float2bfloat16(o[nt][3]);
            *(uint32_t*)(g_aoh + off) = packbf(h2, h3);
            *(uint32_t*)(g_aol + off) =
                packbf(__float2bfloat16(o[nt][2] - __bfloat162float(h2)),
                       __float2bfloat16(o[nt][3] - __bfloat162float(h3)));
        }
    }
}

// ---------------- launch ------------------------------------------------------
extern "C" void kernel_launch(void* const* d_in, const int* in_sizes, int n_in,
                              void* d_out, int out_size) {
    const float* x          = (const float*)d_in[0];
    const float* qkv_w      = (const float*)d_in[1];
    const float* qkv_b      = (const float*)d_in[2];
    const float* proj_w     = (const float*)d_in[3];
    const float* proj_b     = (const float*)d_in[4];
    const float* bias_table = (const float*)d_in[5];
    const int*   rel_idx    = (const int*)d_in[6];
    float* out = (float*)d_out;

    static bool attr_set = false;
    if (!attr_set) {
        cudaFuncSetAttribute(gemm_kernel, cudaFuncAttributeMaxDynamicSharedMemorySize,
                             GEMM_SMEM);
        attr_set = true;
    }

    prep_kernel<<<640, 256>>>(qkv_w, proj_w, bias_table, rel_idx);

    gemm_kernel<<<T_TOK / GBM, 256, GEMM_SMEM>>>(x, nullptr, qkv_b, NQKV, 12, 0);

    dim3 g2(4096, NHD);
    attn_kernel<<<g2, 128>>>();

    gemm_kernel<<<T_TOK / GBM, 256, GEMM_SMEM>>>(nullptr, out, proj_b, DIMC, 4, 1);
}

// round 6
// speedup vs baseline: 1.6856x; 1.1636x over previous
#include <cuda_runtime.h>
#include <cuda_bf16.h>
#include <cstdint>
#include <cstddef>

#define T_TOK 200704          // 4096 * 49 tokens
#define DIMC  192
#define NHD   6
#define HDIM  32
#define NTOK  49
#define NQKV  576
#define SCALEA 0.17677669529663687f
#define BIAS_STRIDE 2404      // 49*49 padded to 16B multiple (floats)

// ---------------- device scratch (static; no runtime allocation) -------------
__device__ __nv_bfloat16 g_qkvh[(size_t)T_TOK * NQKV];   // [b][which][h][tok][d]
__device__ __nv_bfloat16 g_qkvl[(size_t)T_TOK * NQKV];
__device__ __nv_bfloat16 g_aoh[(size_t)T_TOK * DIMC];    // attn out hi [t][c]
__device__ __nv_bfloat16 g_aol[(size_t)T_TOK * DIMC];
__device__ __nv_bfloat16 g_wqkvT_h[NQKV * DIMC];
__device__ __nv_bfloat16 g_wqkvT_l[NQKV * DIMC];
__device__ __nv_bfloat16 g_wprojT_h[DIMC * DIMC];
__device__ __nv_bfloat16 g_wprojT_l[DIMC * DIMC];
__device__ float g_bias6[NHD * BIAS_STRIDE];

// ---------------- helpers ----------------------------------------------------
__device__ __forceinline__ uint32_t packbf(__nv_bfloat16 a, __nv_bfloat16 b) {
    __nv_bfloat162 t(a, b);
    return *reinterpret_cast<uint32_t*>(&t);
}

__device__ __forceinline__ void mma16816(float* c, const uint32_t* a,
                                         uint32_t b0, uint32_t b1) {
    asm volatile(
        "mma.sync.aligned.m16n8k16.row.col.f32.bf16.bf16.f32 "
        "{%0,%1,%2,%3},{%4,%5,%6,%7},{%8,%9},{%0,%1,%2,%3};"
        : "+f"(c[0]), "+f"(c[1]), "+f"(c[2]), "+f"(c[3])
        : "r"(a[0]), "r"(a[1]), "r"(a[2]), "r"(a[3]), "r"(b0), "r"(b1));
}

__device__ __forceinline__ void ldsm4(uint32_t* r, uint32_t addr) {
    asm volatile("ldmatrix.sync.aligned.m8n8.x4.shared.b16 {%0,%1,%2,%3}, [%4];"
                 : "=r"(r[0]), "=r"(r[1]), "=r"(r[2]), "=r"(r[3]) : "r"(addr));
}

__device__ __forceinline__ void ldsm4t(uint32_t* r, uint32_t addr) {
    asm volatile("ldmatrix.sync.aligned.m8n8.x4.trans.shared.b16 {%0,%1,%2,%3}, [%4];"
                 : "=r"(r[0]), "=r"(r[1]), "=r"(r[2]), "=r"(r[3]) : "r"(addr));
}

__device__ __forceinline__ void ldsm2(uint32_t& r0, uint32_t& r1, uint32_t addr) {
    asm volatile("ldmatrix.sync.aligned.m8n8.x2.shared.b16 {%0,%1}, [%2];"
                 : "=r"(r0), "=r"(r1) : "r"(addr));
}

__device__ __forceinline__ void cpa16(uint32_t smem, const void* gptr) {
    asm volatile("cp.async.cg.shared.global [%0], [%1], 16;\n"
                 :: "r"(smem), "l"(gptr));
}
__device__ __forceinline__ void cp_commit() {
    asm volatile("cp.async.commit_group;\n" ::: "memory");
}
__device__ __forceinline__ void cp_wait0() {
    asm volatile("cp.async.wait_group 0;\n" ::: "memory");
}

__device__ __forceinline__ uint32_t s2u(const void* p) {
    return (uint32_t)__cvta_generic_to_shared(p);
}

// ---------------- prep: split weights + pre-gather bias ----------------------
__global__ void prep_kernel(const float* __restrict__ qkv_w,
                            const float* __restrict__ proj_w,
                            const float* __restrict__ bias_table,
                            const int*   __restrict__ rel_idx) {
    const int n1 = NQKV * DIMC, n2 = DIMC * DIMC, n3 = NHD * NTOK * NTOK;
    for (int i = blockIdx.x * blockDim.x + threadIdx.x; i < n1 + n2 + n3;
         i += gridDim.x * blockDim.x) {
        if (i < n1) {
            int n = i / DIMC, k = i % DIMC;
            float w = qkv_w[k * NQKV + n];
            __nv_bfloat16 h = __float2bfloat16(w);
            g_wqkvT_h[i] = h;
            g_wqkvT_l[i] = __float2bfloat16(w - __bfloat162float(h));
        } else if (i < n1 + n2) {
            int j = i - n1;
            int n = j / DIMC, k = j % DIMC;
            float w = proj_w[k * DIMC + n];
            __nv_bfloat16 h = __float2bfloat16(w);
            g_wprojT_h[j] = h;
            g_wprojT_l[j] = __float2bfloat16(w - __bfloat162float(h));
        } else {
            int j = i - n1 - n2;
            int h6 = j / (NTOK * NTOK);
            int rc = j % (NTOK * NTOK);
            g_bias6[h6 * BIAS_STRIDE + rc] = bias_table[rel_idx[rc] * NHD + h6];
        }
    }
}

// ---------------- GEMM ------------------------------------------------------
// mode 0: A = x fp32 (split in prologue), C = qkv bf16 hi/lo, Nc=576, 12 chunks
// mode 1: A = g_aoh/g_aol bf16,           C = out fp32,       Nc=192, 4 chunks
#define GBM   64
#define GSTR  200                       // smem row stride in halves
#define SM_A  (GBM * GSTR)              // halves per A buffer
#define SM_B  (48 * GSTR)               // halves per B buffer
#define GEMM_SMEM ((2 * SM_A + 2 * SM_B) * 2)   // 89600 bytes

__global__ __launch_bounds__(256, 2)
void gemm_kernel(const float* __restrict__ Ax, float* __restrict__ Cout,
                 const float* __restrict__ bias, int Nc, int nChunks, int mode) {
    extern __shared__ __nv_bfloat16 smb[];
    __nv_bfloat16* Ah = smb;
    __nv_bfloat16* Al = smb + SM_A;
    __nv_bfloat16* Bh = smb + 2 * SM_A;
    __nv_bfloat16* Bl = smb + 2 * SM_A + SM_B;

    const __nv_bfloat16* Bgh = mode ? g_wprojT_h : g_wqkvT_h;
    const __nv_bfloat16* Bgl = mode ? g_wprojT_l : g_wqkvT_l;

    const int tid = threadIdx.x;
    const size_t rbase = (size_t)blockIdx.x * GBM;

    // B chunk 0 first (async), then A
    for (int i = tid; i < 48 * 24; i += 256) {
        int row = i / 24, j = i % 24;
        const size_t go = (size_t)row * DIMC + j * 8;
        cpa16(s2u(Bh + row * GSTR + j * 8), Bgh + go);
        cpa16(s2u(Bl + row * GSTR + j * 8), Bgl + go);
    }
    cp_commit();

    if (mode == 0) {
        // A: fp32 x, convert+split into smem
        for (int i = tid; i < GBM * 48; i += 256) {
            int row = i / 48, j = i % 48;
            float4 v = *(const float4*)(Ax + (rbase + row) * DIMC + j * 4);
            __nv_bfloat16 h0 = __float2bfloat16(v.x), h1 = __float2bfloat16(v.y);
            __nv_bfloat16 h2 = __float2bfloat16(v.z), h3 = __float2bfloat16(v.w);
            __nv_bfloat16 l0 = __float2bfloat16(v.x - __bfloat162float(h0));
            __nv_bfloat16 l1 = __float2bfloat16(v.y - __bfloat162float(h1));
            __nv_bfloat16 l2 = __float2bfloat16(v.z - __bfloat162float(h2));
            __nv_bfloat16 l3 = __float2bfloat16(v.w - __bfloat162float(h3));
            *(uint2*)(Ah + row * GSTR + j * 4) = make_uint2(packbf(h0, h1), packbf(h2, h3));
            *(uint2*)(Al + row * GSTR + j * 4) = make_uint2(packbf(l0, l1), packbf(l2, l3));
        }
    } else {
        for (int i = tid; i < GBM * 24; i += 256) {
            int row = i / 24, j = i % 24;
            const size_t go = (rbase + row) * DIMC + j * 8;
            cpa16(s2u(Ah + row * GSTR + j * 8), g_aoh + go);
            cpa16(s2u(Al + row * GSTR + j * 8), g_aol + go);
        }
        cp_commit();
    }
    cp_wait0();
    __syncthreads();

    const int lane = tid & 31, warp = tid >> 5;
    const int g = lane >> 2, tg = lane & 3;
    const int m0 = (warp >> 1) * 16;        // 4 warps over M=64
    const int n0 = (warp & 1) * 24;         // 2 warps over 48-col chunk

    const int aRow = m0 + (lane & 15);
    const int aK   = (lane >> 4) * 8;
    const int b4Row = n0 + (lane & 7) + ((lane >> 4) << 3);
    const int bK    = ((lane >> 3) & 1) * 8;
    const int b2Row = n0 + 16 + (lane & 7);

    const uint32_t aBaseH  = s2u(Ah + aRow * GSTR + aK);
    const uint32_t aBaseL  = aBaseH + SM_A * 2;
    const uint32_t b4BaseH = s2u(Bh + b4Row * GSTR + bK);
    const uint32_t b4BaseL = b4BaseH + SM_B * 2;
    const uint32_t b2BaseH = s2u(Bh + b2Row * GSTR + bK);
    const uint32_t b2BaseL = b2BaseH + SM_B * 2;

    for (int c = 0; c < nChunks; c++) {
        float acc[3][4];
#pragma unroll
        for (int nt = 0; nt < 3; nt++)
#pragma unroll
            for (int r = 0; r < 4; r++) acc[nt][r] = 0.f;

        // fragments hoisted across the 3 split-parts: 6 LDSM feed 9 MMAs per kk
#pragma unroll
        for (int kk = 0; kk < 12; kk++) {
            uint32_t ah[4], al[4], bh[6], bl[6];
            ldsm4(ah, aBaseH + kk * 32);
            ldsm4(al, aBaseL + kk * 32);
            ldsm4(bh, b4BaseH + kk * 32);
            ldsm2(bh[4], bh[5], b2BaseH + kk * 32);
            ldsm4(bl, b4BaseL + kk * 32);
            ldsm2(bl[4], bl[5], b2BaseL + kk * 32);
#pragma unroll
            for (int nt = 0; nt < 3; nt++) {
                mma16816(acc[nt], ah, bh[2 * nt], bh[2 * nt + 1]);
                mma16816(acc[nt], al, bh[2 * nt], bh[2 * nt + 1]);
                mma16816(acc[nt], ah, bl[2 * nt], bl[2 * nt + 1]);
            }
        }
        __syncthreads();                    // done reading B chunk c

        if (c + 1 < nChunks) {              // prefetch next B chunk
            for (int i = tid; i < 48 * 24; i += 256) {
                int row = i / 24, j = i % 24;
                const size_t go = (size_t)((c + 1) * 48 + row) * DIMC + j * 8;
                cpa16(s2u(Bh + row * GSTR + j * 8), Bgh + go);
                cpa16(s2u(Bl + row * GSTR + j * 8), Bgl + go);
            }
            cp_commit();
        }

        // epilogue for chunk c (overlaps in-flight cp.async)
        const int colBase = c * 48 + n0;
        const size_t r0 = rbase + m0 + g;
        if (mode == 0) {
#pragma unroll
            for (int nt = 0; nt < 3; nt++) {
                int col = colBase + nt * 8 + tg * 2;
                int which = col / DIMC;
                int rem = col - which * DIMC;
                int hh = rem >> 5, d = rem & 31;
                float bb0 = bias[col], bb1 = bias[col + 1];
#pragma unroll
                for (int rr = 0; rr < 2; rr++) {
                    size_t r = r0 + rr * 8;
                    int bwin = (int)(r / NTOK);
                    int tok = (int)(r - (size_t)bwin * NTOK);
                    size_t off = ((((size_t)bwin * 3 + which) * NHD + hh) * NTOK + tok)
                                 * HDIM + d;
                    float v0 = acc[nt][rr * 2 + 0] + bb0;
                    float v1 = acc[nt][rr * 2 + 1] + bb1;
                    __nv_bfloat16 h0 = __float2bfloat16(v0);
                    __nv_bfloat16 h1 = __float2bfloat16(v1);
                    *(uint32_t*)(g_qkvh + off) = packbf(h0, h1);
                    *(uint32_t*)(g_qkvl + off) =
                        packbf(__float2bfloat16(v0 - __bfloat162float(h0)),
                               __float2bfloat16(v1 - __bfloat162float(h1)));
                }
            }
        } else {
#pragma unroll
            for (int nt = 0; nt < 3; nt++) {
                int col = colBase + nt * 8 + tg * 2;
                float bb0 = bias[col], bb1 = bias[col + 1];
                *(float2*)(Cout + r0 * Nc + col) =
                    make_float2(acc[nt][0] + bb0, acc[nt][1] + bb1);
                *(float2*)(Cout + (r0 + 8) * Nc + col) =
                    make_float2(acc[nt][2] + bb0, acc[nt][3] + bb1);
            }
        }

        if (c + 1 < nChunks) {
            cp_wait0();
            __syncthreads();
        }
    }
}

// ---------------- attention: one CTA per (2 windows, head) -------------------
// dynamic smem: 12 qkv buffers (2 windows x Qh Ql Kh Kl Vh Vl, 49x40 halves,
// 80B row stride) + one shared bias tile (head-identical across both windows)
#define ABUF 1960                 // halves per buffer
#define AB_B 3920                 // bytes per buffer
#define ATTN_SMEM (12 * AB_B + BIAS_STRIDE * 4)   // 56656 bytes

__global__ __launch_bounds__(256)
void attn_kernel() {
    extern __shared__ char dsm[];
    __nv_bfloat16* sQKV = (__nv_bfloat16*)dsm;
    float* sBias = (float*)(dsm + 12 * AB_B);

    const int b = blockIdx.x, h = blockIdx.y;   // b = window pair
    const int tid = threadIdx.x;
    const uint32_t sBase = s2u(sQKV);
    const uint32_t sBiasU = s2u(sBias);

    // ---- cp.async: 12 qkv slabs (each 3136 B contiguous) + bias ------------
    {
        const size_t slabStride = (size_t)NTOK * HDIM;               // 1568
        const float* biasg = g_bias6 + h * BIAS_STRIDE;
        for (int i = tid; i < 12 * 196 + 601; i += 256) {
            if (i < 12 * 196) {
                int s = i / 196, j = i - s * 196;
                int wi = s / 6, sb = s - wi * 6;
                int which = sb >> 1;
                const size_t base =
                    ((size_t)(b * 2 + wi) * 3 * NHD + h) * slabStride
                    + (size_t)which * NHD * slabStride;
                const __nv_bfloat16* src =
                    ((sb & 1) ? g_qkvl : g_qkvh) + base + j * 8;
                cpa16(sBase + s * AB_B + (j >> 2) * 80 + (j & 3) * 16, src);
            } else {
                int j = i - 12 * 196;
                cpa16(sBiasU + j * 16, biasg + j * 4);
            }
        }
        cp_commit();
    }

    const int lane = tid & 31, w = tid >> 5;
    const int wi = w >> 2, wl = w & 3;          // window index, warp-in-window
    const int g = lane >> 2, tg = lane & 3;
    const uint32_t qkvB = sBase + wi * (6 * AB_B);

    // ldmatrix lane offsets (bytes), rows clamped to 48 (real data; masked later)
    const int qRow = wl * 16 + (lane & 15);
    const uint32_t qOff = (uint32_t)(min(qRow, 48) * 80 + (lane >> 4) * 16);
    const int kR = (lane & 7) + ((lane >> 4) << 3);
    const int kC = ((lane >> 3) & 1) * 16;
    const int vR0 = (lane & 7) + (((lane >> 3) & 1) << 3);
    const int vC = (lane >> 4) * 16;

    cp_wait0();
    __syncthreads();

    // ---- S = Q K^T (3-term split). 8 n-tiles (cols 0..63) -------------------
    float s[8][4];
#pragma unroll
    for (int nt = 0; nt < 8; nt++)
#pragma unroll
        for (int r = 0; r < 4; r++) s[nt][r] = 0.f;

#pragma unroll
    for (int part = 0; part < 3; part++) {
        const uint32_t qB = qkvB + ((part == 1) ? AB_B : 0) + qOff;
        const uint32_t kB = qkvB + 2 * AB_B + ((part == 2) ? AB_B : 0);
#pragma unroll
        for (int kk = 0; kk < 2; kk++) {
            uint32_t a[4];
            ldsm4(a, qB + kk * 32);
#pragma unroll
            for (int p = 0; p < 4; p++) {
                uint32_t bfr[4];
                ldsm4(bfr, kB + (uint32_t)(min(p * 16 + kR, 48) * 80 + kC) + kk * 32);
                mma16816(s[2 * p], a, bfr[0], bfr[1]);
                mma16816(s[2 * p + 1], a, bfr[2], bfr[3]);
            }
        }
    }

    // ---- scale + bias + mask ----
    const int r0 = wl * 16 + g, r1 = r0 + 8;
#pragma unroll
    for (int nt = 0; nt < 8; nt++) {
#pragma unroll
        for (int j = 0; j < 2; j++) {
            int col = nt * 8 + tg * 2 + j;
            if (col < NTOK) {
                s[nt][j]     = s[nt][j]     * SCALEA + (r0 < NTOK ? sBias[r0 * NTOK + col] : 0.f);
                s[nt][2 + j] = s[nt][2 + j] * SCALEA + (r1 < NTOK ? sBias[r1 * NTOK + col] : 0.f);
            } else {
                s[nt][j] = -1e30f;
                s[nt][2 + j] = -1e30f;
            }
        }
    }

    // ---- softmax ----
    float m0 = -1e30f, m1 = -1e30f;
#pragma unroll
    for (int nt = 0; nt < 8; nt++) {
        m0 = fmaxf(m0, fmaxf(s[nt][0], s[nt][1]));
        m1 = fmaxf(m1, fmaxf(s[nt][2], s[nt][3]));
    }
    m0 = fmaxf(m0, __shfl_xor_sync(0xffffffffu, m0, 1));
    m0 = fmaxf(m0, __shfl_xor_sync(0xffffffffu, m0, 2));
    m1 = fmaxf(m1, __shfl_xor_sync(0xffffffffu, m1, 1));
    m1 = fmaxf(m1, __shfl_xor_sync(0xffffffffu, m1, 2));
    float d0 = 0.f, d1 = 0.f;
#pragma unroll
    for (int nt = 0; nt < 8; nt++) {
        s[nt][0] = __expf(s[nt][0] - m0); d0 += s[nt][0];
        s[nt][1] = __expf(s[nt][1] - m0); d0 += s[nt][1];
        s[nt][2] = __expf(s[nt][2] - m1); d1 += s[nt][2];
        s[nt][3] = __expf(s[nt][3] - m1); d1 += s[nt][3];
    }
    d0 += __shfl_xor_sync(0xffffffffu, d0, 1);
    d0 += __shfl_xor_sync(0xffffffffu, d0, 2);
    d1 += __shfl_xor_sync(0xffffffffu, d1, 1);
    d1 += __shfl_xor_sync(0xffffffffu, d1, 2);
    const float inv0 = 1.f / d0, inv1 = 1.f / d1;

    // ---- P fragments (hi/lo split); S-accum layout == A-fragment layout -----
    uint32_t aPh[4][4], aPl[4][4];
#pragma unroll
    for (int kc = 0; kc < 4; kc++) {
#pragma unroll
        for (int t2 = 0; t2 < 2; t2++) {
            int tile = 2 * kc + t2;
            float p0 = s[tile][0] * inv0, p1 = s[tile][1] * inv0;
            float p2 = s[tile][2] * inv1, p3 = s[tile][3] * inv1;
            __nv_bfloat16 h0 = __float2bfloat16(p0), h1 = __float2bfloat16(p1);
            __nv_bfloat16 h2 = __float2bfloat16(p2), h3 = __float2bfloat16(p3);
            aPh[kc][t2]     = packbf(h0, h1);
            aPh[kc][t2 + 2] = packbf(h2, h3);
            aPl[kc][t2]     = packbf(__float2bfloat16(p0 - __bfloat162float(h0)),
                                     __float2bfloat16(p1 - __bfloat162float(h1)));
            aPl[kc][t2 + 2] = packbf(__float2bfloat16(p2 - __bfloat162float(h2)),
                                     __float2bfloat16(p3 - __bfloat162float(h3)));
        }
    }
    // A-fragment reg order {r0k0, r8k0, r0k8, r8k8}: swap regs 1<->2
#pragma unroll
    for (int kc = 0; kc < 4; kc++) {
        uint32_t t = aPh[kc][1]; aPh[kc][1] = aPh[kc][2]; aPh[kc][2] = t;
        t = aPl[kc][1]; aPl[kc][1] = aPl[kc][2]; aPl[kc][2] = t;
    }

    // ---- O = P V (3-term split), V via ldmatrix.trans -----------------------
    float o[4][4];
#pragma unroll
    for (int nt = 0; nt < 4; nt++)
#pragma unroll
        for (int r = 0; r < 4; r++) o[nt][r] = 0.f;

#pragma unroll
    for (int part = 0; part < 3; part++) {
        const uint32_t (*Ap)[4] = (part == 1) ? aPl : aPh;
        const uint32_t vB = qkvB + 4 * AB_B + ((part == 2) ? AB_B : 0);
#pragma unroll
        for (int kc = 0; kc < 4; kc++) {
            const uint32_t rowOff = (uint32_t)(min(vR0 + kc * 16, 48) * 80 + vC);
#pragma unroll
            for (int dh = 0; dh < 2; dh++) {
                uint32_t bv[4];
                ldsm4t(bv, vB + rowOff + dh * 32);
                mma16816(o[dh * 2 + 0], Ap[kc], bv[0], bv[1]);
                mma16816(o[dh * 2 + 1], Ap[kc], bv[2], bv[3]);
            }
        }
    }

    // ---- store bf16 hi/lo ----
    const size_t bw = (size_t)(b * 2 + wi);
#pragma unroll
    for (int nt = 0; nt < 4; nt++) {
        int d = h * HDIM + nt * 8 + tg * 2;
        if (r0 < NTOK) {
            size_t off = (bw * NTOK + r0) * DIMC + d;
            __nv_bfloat16 h0 = __float2bfloat16(o[nt][0]);
            __nv_bfloat16 h1 = __float2bfloat16(o[nt][1]);
            *(uint32_t*)(g_aoh + off) = packbf(h0, h1);
            *(uint32_t*)(g_aol + off) =
                packbf(__float2bfloat16(o[nt][0] - __bfloat162float(h0)),
                       __float2bfloat16(o[nt][1] - __bfloat162float(h1)));
        }
        if (r1 < NTOK) {
            size_t off = (bw * NTOK + r1) * DIMC + d;
            __nv_bfloat16 h2 = __float2bfloat16(o[nt][2]);
            __nv_bfloat16 h3 = __float2bfloat16(o[nt][3]);
            *(uint32_t*)(g_aoh + off) = packbf(h2, h3);
            *(uint32_t*)(g_aol + off) =
                packbf(__float2bfloat16(o[nt][2] - __bfloat162float(h2)),
                       __float2bfloat16(o[nt][3] - __bfloat162float(h3)));
        }
    }
}

// ---------------- launch ------------------------------------------------------
extern "C" void kernel_launch(void* const* d_in, const int* in_sizes, int n_in,
                              void* d_out, int out_size) {
    const float* x          = (const float*)d_in[0];
    const float* qkv_w      = (const float*)d_in[1];
    const float* qkv_b      = (const float*)d_in[2];
    const float* proj_w     = (const float*)d_in[3];
    const float* proj_b     = (const float*)d_in[4];
    const float* bias_table = (const float*)d_in[5];
    const int*   rel_idx    = (const int*)d_in[6];
    float* out = (float*)d_out;

    static bool attr_set = false;
    if (!attr_set) {
        cudaFuncSetAttribute(gemm_kernel, cudaFuncAttributeMaxDynamicSharedMemorySize,
                             GEMM_SMEM);
        cudaFuncSetAttribute(attn_kernel, cudaFuncAttributeMaxDynamicSharedMemorySize,
                             ATTN_SMEM);
        attr_set = true;
    }

    prep_kernel<<<640, 256>>>(qkv_w, proj_w, bias_table, rel_idx);

    gemm_kernel<<<T_TOK / GBM, 256, GEMM_SMEM>>>(x, nullptr, qkv_b, NQKV, 12, 0);

    dim3 g2(2048, NHD);
    attn_kernel<<<g2, 256, ATTN_SMEM>>>();

    gemm_kernel<<<T_TOK / GBM, 256, GEMM_SMEM>>>(nullptr, out, proj_b, DIMC, 4, 1);
}